// round 12
// baseline (speedup 1.0000x reference)
#include <cuda_runtime.h>
#include <cuda_fp16.h>

#define TPB     256
#define NBLOCKS 1184       // grid-stride; covers 148 SMs at 4-8 CTAs/SM

// Mixed-precision weight pack:
//  fp32: W1 (3x8 rm) [0:24), b1 [24:32), wq [32]
//  half2 (duplicated): W2 (8x4 rm) h[0:32), b2 h[32:36), W3 h[36:40), b3 h[40]
struct WPack {
    float  f[33];
    float  pad;          // keep half2 array 4B-aligned region tidy
    __half2 h[41];
};
__device__    WPack g_stage;
__constant__  WPack cwp;

__global__ void gather_weights(
    const float* __restrict__ W1, const float* __restrict__ b1,
    const float* __restrict__ W2, const float* __restrict__ b2,
    const float* __restrict__ W3, const float* __restrict__ b3,
    const float* __restrict__ w)
{
    const int i = threadIdx.x;
    // fp32 section
    if (i < 24)       g_stage.f[i] = W1[i];
    else if (i < 32)  g_stage.f[i] = b1[i - 24];
    else if (i == 32) g_stage.f[i] = w[0];
    // half2 section (lane-duplicated)
    const int j = i - 64;   // threads 64.. handle half weights
    if (j >= 0 && j < 41) {
        float s;
        if (j < 32)       s = W2[j];
        else if (j < 36)  s = b2[j - 32];
        else if (j < 40)  s = W3[j - 36];
        else              s = b3[0];
        g_stage.h[j] = __floats2half2_rn(s, s);
    }
}

__device__ __forceinline__ float tanha(float x) {
    float y;
    asm("tanh.approx.f32 %0, %1;" : "=f"(y) : "f"(x));
    return y;
}
__device__ __forceinline__ __half2 tanh2a(__half2 x) {
    unsigned xi = *reinterpret_cast<unsigned*>(&x);
    unsigned yi;
    asm("tanh.approx.f16x2 %0, %1;" : "=r"(yi) : "r"(xi));
    return *reinterpret_cast<__half2*>(&yi);
}

// Two rows at once. v = (x0_r0, x1_r0, x0_r1, x1_r1)
__device__ __forceinline__ float2 eval_pair(float4 v) {
    const float wq = cwp.f[32];

    // quantum feature in fp32
    const float qa = __sinf(v.x) * __sinf(v.y + wq);
    const float qb = __sinf(v.z) * __sinf(v.w + wq);

    // ---- layer 1 in fp32 (both rows, scalar FFMA + tanh.approx.f32) ----
    // h1 packed per-j as half2{row0, row1} for the fp16 layers below.
    __half2 h1[8];
#pragma unroll
    for (int j = 0; j < 8; ++j) {
        float a = fmaf(cwp.f[0 * 8 + j], v.x, cwp.f[24 + j]);
        a = fmaf(cwp.f[1 * 8 + j], v.y, a);
        a = fmaf(cwp.f[2 * 8 + j], qa, a);
        float b = fmaf(cwp.f[0 * 8 + j], v.z, cwp.f[24 + j]);
        b = fmaf(cwp.f[1 * 8 + j], v.w, b);
        b = fmaf(cwp.f[2 * 8 + j], qb, b);
        h1[j] = __floats2half2_rn(tanha(a), tanha(b));   // F2FP pack
    }

    // ---- layer 2 in packed fp16 (HFMA2 + tanh.approx.f16x2) ----
    __half2 h2[4];
#pragma unroll
    for (int j = 0; j < 4; ++j) {
        __half2 acc = cwp.h[32 + j];                      // b2
#pragma unroll
        for (int i = 0; i < 8; ++i) acc = __hfma2(h1[i], cwp.h[i * 4 + j], acc);
        h2[j] = tanh2a(acc);
    }

    // ---- layer 3 in packed fp16 ----
    __half2 o = cwp.h[40];                                // b3
#pragma unroll
    for (int j = 0; j < 4; ++j) o = __hfma2(h2[j], cwp.h[36 + j], o);

    return make_float2(__low2float(o), __high2float(o));
}

__global__ void __launch_bounds__(TPB, 4) qnn_kernel(
    const float4* __restrict__ in,   // 2 rows per float4
    float2*       __restrict__ out,  // 2 outputs per float2
    int npairs, int nrows,
    const float* __restrict__ in_scalar, float* __restrict__ out_scalar)
{
    const int t      = blockIdx.x * TPB + threadIdx.x;
    const int stride = NBLOCKS * TPB;

    for (int p = t; p < npairs; p += stride) {
        out[p] = eval_pair(__ldg(in + p));
    }

    // odd trailing row: duplicated pair, keep low lane
    if ((nrows & 1) && t == 0) {
        const float x0 = __ldg(in_scalar + (nrows - 1) * 2);
        const float x1 = __ldg(in_scalar + (nrows - 1) * 2 + 1);
        out_scalar[nrows - 1] = eval_pair(make_float4(x0, x1, x0, x1)).x;
    }
}

extern "C" void kernel_launch(void* const* d_in, const int* in_sizes, int n_in,
                              void* d_out, int out_size)
{
    const float* in = (const float*)d_in[0];
    const int nrows  = in_sizes[0] / 2;
    const int npairs = nrows / 2;

    gather_weights<<<1, 128>>>(
        (const float*)d_in[1], (const float*)d_in[2],
        (const float*)d_in[3], (const float*)d_in[4],
        (const float*)d_in[5], (const float*)d_in[6],
        (const float*)d_in[7]);
    void* stage_addr = nullptr;
    cudaGetSymbolAddress(&stage_addr, g_stage);
    cudaMemcpyToSymbolAsync(cwp, stage_addr, sizeof(WPack), 0,
                            cudaMemcpyDeviceToDevice, 0);

    qnn_kernel<<<NBLOCKS, TPB>>>(
        (const float4*)in, (float2*)d_out,
        npairs, nrows,
        in, (float*)d_out);
}

// round 15
// speedup vs baseline: 1.0915x; 1.0915x over previous
#include <cuda_runtime.h>

#define TPB     256
#define NBLOCKS 1184       // grid-stride; 148 SMs x 4+ CTAs/SM

// SMEM weight layout:
// [0:24)  W1 (3x8 rm)   [24:32) b1
// [32:64) W2 (8x4 rm)   [64:68) b2
// [68:72) W3            [72] b3   [73] wq
__device__ __forceinline__ float tanha(float x) {
    float y;
    asm("tanh.approx.f32 %0, %1;" : "=f"(y) : "f"(x));
    return y;
}

__device__ __forceinline__ float2 eval_pair(float4 v, const float* __restrict__ sw) {
    const float wq = sw[73];
    const float qa = __sinf(v.x) * __sinf(v.y + wq);
    const float qb = __sinf(v.z) * __sinf(v.w + wq);

    float h1a[8], h1b[8];
#pragma unroll
    for (int j = 0; j < 8; ++j) {
        const float w0 = sw[0 * 8 + j], w1 = sw[1 * 8 + j], w2 = sw[2 * 8 + j];
        const float bb = sw[24 + j];
        float a = fmaf(w0, v.x, bb); a = fmaf(w1, v.y, a); a = fmaf(w2, qa, a);
        float b = fmaf(w0, v.z, bb); b = fmaf(w1, v.w, b); b = fmaf(w2, qb, b);
        h1a[j] = tanha(a);
        h1b[j] = tanha(b);
    }

    float h2a[4], h2b[4];
#pragma unroll
    for (int j = 0; j < 4; ++j) {
        const float bb = sw[64 + j];
        float a = bb, b = bb;
#pragma unroll
        for (int i = 0; i < 8; ++i) {
            const float w = sw[32 + i * 4 + j];
            a = fmaf(h1a[i], w, a);
            b = fmaf(h1b[i], w, b);
        }
        h2a[j] = tanha(a);
        h2b[j] = tanha(b);
    }

    float oa = sw[72], ob = sw[72];
#pragma unroll
    for (int j = 0; j < 4; ++j) {
        const float w = sw[68 + j];
        oa = fmaf(h2a[j], w, oa);
        ob = fmaf(h2b[j], w, ob);
    }
    return make_float2(oa, ob);
}

__global__ void __launch_bounds__(TPB, 4) qnn_kernel(
    const float4* __restrict__ in,   // 2 rows per float4
    float2*       __restrict__ out,  // 2 outputs per float2
    int npairs, int nrows,
    const float* __restrict__ W1, const float* __restrict__ b1,
    const float* __restrict__ W2, const float* __restrict__ b2,
    const float* __restrict__ W3, const float* __restrict__ b3,
    const float* __restrict__ w,
    const float* __restrict__ in_scalar, float* __restrict__ out_scalar)
{
    __shared__ float sw[80];

    // Cooperative weight load: 74 scalars, broadcast-read afterwards.
    {
        const int i = threadIdx.x;
        if (i < 24)       sw[i] = W1[i];
        else if (i < 32)  sw[i] = b1[i - 24];
        else if (i < 64)  sw[i] = W2[i - 32];
        else if (i < 68)  sw[i] = b2[i - 64];
        else if (i < 72)  sw[i] = W3[i - 68];
        else if (i == 72) sw[i] = b3[0];
        else if (i == 73) sw[i] = w[0];
    }
    __syncthreads();

    const int t      = blockIdx.x * TPB + threadIdx.x;
    const int stride = NBLOCKS * TPB;

    // 2-pair body: one set of weight reads feeds 4 rows.
    int p = t;
    for (; p + stride < npairs; p += 2 * stride) {
        const float4 v0 = __ldg(in + p);
        const float4 v1 = __ldg(in + p + stride);
        out[p]          = eval_pair(v0, sw);
        out[p + stride] = eval_pair(v1, sw);
    }
    if (p < npairs) {
        out[p] = eval_pair(__ldg(in + p), sw);
    }

    // odd trailing row
    if ((nrows & 1) && t == 0) {
        const float x0 = __ldg(in_scalar + (nrows - 1) * 2);
        const float x1 = __ldg(in_scalar + (nrows - 1) * 2 + 1);
        out_scalar[nrows - 1] = eval_pair(make_float4(x0, x1, x0, x1), sw).x;
    }
}

extern "C" void kernel_launch(void* const* d_in, const int* in_sizes, int n_in,
                              void* d_out, int out_size)
{
    const float* in = (const float*)d_in[0];
    const int nrows  = in_sizes[0] / 2;
    const int npairs = nrows / 2;

    qnn_kernel<<<NBLOCKS, TPB>>>(
        (const float4*)in, (float2*)d_out,
        npairs, nrows,
        (const float*)d_in[1], (const float*)d_in[2],
        (const float*)d_in[3], (const float*)d_in[4],
        (const float*)d_in[5], (const float*)d_in[6],
        (const float*)d_in[7],
        in, (float*)d_out);
}